// round 16
// baseline (speedup 1.0000x reference)
#include <cuda_runtime.h>
#include <math_constants.h>

#define BATCH 2
#define NPTS 1024
#define KNN 8
#define TI 2
#define THREADS 256
#define NW (THREADS / 32)

// FACTOR_A = 180 / (15 * pi) = 12/pi
#define FACTOR_A 3.8197186342054885f

// Single-MUFU approximations.
__device__ __forceinline__ float fsqrt_fast(float x) {
    float r;
    asm("sqrt.approx.f32 %0, %1;" : "=f"(r) : "f"(x));
    return r;
}
__device__ __forceinline__ float frsqrt_fast(float x) {
    float r;
    asm("rsqrt.approx.f32 %0, %1;" : "=f"(r) : "f"(x));
    return r;
}

// Branchless acos, Abramowitz-Stegun 4.4.45 (|err| <= 6.7e-5 rad). Clamps internally.
// facos(NaN) = pi (fminf drops NaN -> ax=1 -> s=0; NaN>=0 false -> pi); the
// diagonal's angle = |pi - pi| = 0 depends on this, so keep the SETP/SEL form.
__device__ __forceinline__ float facos(float x) {
    float ax = fminf(fabsf(x), 1.0f);
    float p = fmaf(ax, -0.0187293f, 0.0742610f);
    p = fmaf(ax, p, -0.2121144f);
    p = fmaf(ax, p, 1.5707288f);
    float s = fsqrt_fast(1.0f - ax) * p;
    return (x >= 0.0f) ? s : (CUDART_PI_F - s);
}

// FACTOR_A * acos(x); pi * FACTOR_A == 12 exactly.
__device__ __forceinline__ float facos12(float x) {
    float ax = fminf(fabsf(x), 1.0f);
    float p = fmaf(ax, -0.0187293f * FACTOR_A, 0.0742610f * FACTOR_A);
    p = fmaf(ax, p, -0.2121144f * FACTOR_A);
    p = fmaf(ax, p, 1.5707288f * FACTOR_A);
    float s = fsqrt_fast(1.0f - ax) * p;
    return (x >= 0.0f) ? s : (12.0f - s);
}

// min-blocks=4 pins the reg budget to exactly 64 (65536/256/4): the allocation
// under which ptxas keeps the 24 rk values register-resident (R10/R12/R15).
// 48-reg forcing spills (R9); unpinned 58 regs sinks rkv LDS into the hot loop
// (R11); splitting into two kernels serializes + re-sinks (R13).
__global__ __launch_bounds__(THREADS, 4)
void gse_kernel(const float* __restrict__ points,
                const float* __restrict__ normals,
                float* __restrict__ cat_out,   // [B,N,N,3]
                float* __restrict__ a_out)     // [B,N,N,K]
{
    __shared__ float4   P[NPTS];          // x, y, z, |p|^2 (strict rounding)
    __shared__ float4   Nn[NPTS];         // normalized normal (x,y,z), .w pad
    __shared__ unsigned wval[NW * KNN];   // per-warp top-8 candidate dist-bits
    __shared__ unsigned widx[NW * KNN];
    __shared__ float    rkv[KNN][3];      // normalized ref vectors
    __shared__ float    cbuf[NW][96];     // per-WARP cat staging (384 B each)

    const int b    = blockIdx.x >> 9;            // N/TI = 512 blocks per batch
    const int i0   = (blockIdx.x & 511) * TI;
    const int tid  = threadIdx.x;
    const int lane = tid & 31;
    const int wid  = tid >> 5;

    // ---- load batch points/normals into smem ----
    const float* pb = points  + (size_t)b * NPTS * 3;
    const float* nb = normals + (size_t)b * NPTS * 3;
    for (int j = tid; j < NPTS; j += THREADS) {
        float x = pb[3 * j], y = pb[3 * j + 1], z = pb[3 * j + 2];
        // strict emulation of jnp.sum(p*p,-1): ((x*x)+(y*y))+(z*z), each rounded
        float sqs = __fadd_rn(__fadd_rn(__fmul_rn(x, x), __fmul_rn(y, y)),
                              __fmul_rn(z, z));
        P[j] = make_float4(x, y, z, sqs);
        float nx = nb[3 * j], ny = nb[3 * j + 1], nz = nb[3 * j + 2];
        float rn = __fdividef(1.0f, sqrtf(nx * nx + ny * ny + nz * nz));
        Nn[j] = make_float4(nx * rn, ny * rn, nz * rn, 0.0f);
    }
    __syncthreads();

    for (int ii = 0; ii < TI; ii++) {
        const int i = i0 + ii;
        const float4 Pi = P[i];
        const float pix = Pi.x, piy = Pi.y, piz = Pi.z, sqis = Pi.w;

        // ---- phase A: strict fp32 selection distances (bit-exact vs jax) ----
        float v[4]; int ix[4];
        #pragma unroll
        for (int s = 0; s < 4; s++) {
            int j = tid + s * THREADS;
            float4 Pj = P[j];
            float dot = __fadd_rn(__fadd_rn(__fmul_rn(pix, Pj.x),
                                            __fmul_rn(piy, Pj.y)),
                                  __fmul_rn(piz, Pj.z));
            float d2 = __fsub_rn(__fadd_rn(sqis, Pj.w), __fmul_rn(2.0f, dot));
            float dist = __fsqrt_rn(fmaxf(d2, 0.0f));
            v[s]  = (j == i) ? CUDART_INF_F : dist;  // drop self (== idx[...,0])
            ix[s] = j;
        }

        // ---- phase B1: sort-4 then redux-based top-8 extraction ----
        #define CSWAP(a, bb)                                                  \
            {                                                                 \
                bool sw = (v[bb] < v[a]) ||                                   \
                          (v[bb] == v[a] && ix[bb] < ix[a]);                  \
                float tv = sw ? v[bb] : v[a];                                 \
                v[bb] = sw ? v[a] : v[bb];  v[a] = tv;                        \
                int ti = sw ? ix[bb] : ix[a];                                 \
                ix[bb] = sw ? ix[a] : ix[bb]; ix[a] = ti;                     \
            }
        CSWAP(0, 1) CSWAP(2, 3) CSWAP(0, 2) CSWAP(1, 3) CSWAP(1, 2)
        #undef CSWAP

        #pragma unroll
        for (int k = 0; k < KNN; k++) {
            unsigned fb   = __float_as_uint(v[0]);     // nonneg -> bits monotonic
            unsigned minb = __reduce_min_sync(0xffffffffu, fb);
            unsigned cand = (fb == minb) ? (unsigned)ix[0] : 0xffffffffu;
            unsigned wmin = __reduce_min_sync(0xffffffffu, cand);
            if (fb == minb && (unsigned)ix[0] == wmin) {   // unique winner pops
                v[0] = v[1]; ix[0] = ix[1];
                v[1] = v[2]; ix[1] = ix[2];
                v[2] = v[3]; ix[2] = ix[3];
                v[3] = CUDART_INF_F;
            }
            if (lane == 0) { wval[wid * KNN + k] = minb; widx[wid * KNN + k] = wmin; }
        }
        __syncthreads();

        // ---- phase B2: warp 0 merges 64 candidates; winners build rkv inline ----
        if (wid == 0) {
            unsigned mv0 = wval[lane],  mv1 = wval[lane + 32];
            unsigned id0 = widx[lane],  id1 = widx[lane + 32];
            int myj = 0;
            #pragma unroll
            for (int k = 0; k < KNN; k++) {
                bool sel1 = (mv1 < mv0) || (mv1 == mv0 && id1 < id0);
                unsigned fv = sel1 ? mv1 : mv0;
                unsigned fi = sel1 ? id1 : id0;
                unsigned minb = __reduce_min_sync(0xffffffffu, fv);
                unsigned cand = (fv == minb) ? fi : 0xffffffffu;
                unsigned wmin = __reduce_min_sync(0xffffffffu, cand);
                if (fv == minb && fi == wmin) {
                    if (sel1) mv1 = 0xffffffffu; else mv0 = 0xffffffffu;
                }
                if (lane == k) myj = (int)wmin;   // wmin is warp-uniform
            }
            if (lane < KNN) {
                float rx = P[myj].x - pix, ry = P[myj].y - piy, rz = P[myj].z - piz;
                float rinv = frsqrt_fast(rx * rx + ry * ry + rz * rz);
                rkv[lane][0] = rx * rinv;
                rkv[lane][1] = ry * rinv;
                rkv[lane][2] = rz * rinv;
            }
        }
        __syncthreads();

        float rkx[KNN], rky[KNN], rkz[KNN];
        #pragma unroll
        for (int k = 0; k < KNN; k++) {
            rkx[k] = rkv[k][0];
            rky[k] = rkv[k][1];
            rkz[k] = rkv[k][2];
        }

        const float4 Ni = Nn[i];
        const float nix = Ni.x, niy = Ni.y, niz = Ni.z;   // unit-length
        float* catRow = cat_out + ((size_t)(b * NPTS + i)) * NPTS * 3;
        float* aRow   = a_out   + ((size_t)(b * NPTS + i)) * NPTS * KNN;

        // ---- phase C: full pair row (no per-j diagonal branches; fixed after) ----
        for (int it = 0; it < NPTS / THREADS; it++) {
            const int j = tid + it * THREADS;
            float4 Pj = P[j];
            float4 Nj = Nn[j];
            float dx = Pj.x - pix, dy = Pj.y - piy, dz = Pj.z - piz;
            float dd = fmaf(dx, dx, fmaf(dy, dy, dz * dz));
            float linv = frsqrt_fast(dd);           // inf on diagonal
            float dist = dd * linv * 5.0f;          // NaN on diagonal; fixed below

            // diagonal: ci = cj = NaN -> facos = pi both -> angle = 0 (= ref)
            float doti = fmaf(nix, dx, fmaf(niy, dy, niz * dz));
            float radij = facos(doti * linv);

            float dotj = -fmaf(Nj.x, dx, fmaf(Nj.y, dy, Nj.z * dz));
            float radji = facos(dotj * linv);

            float angle = fabsf(radij - radji);

            // seta from pre-normalized normals (never NaN for these inputs)
            float seta = facos(fmaf(nix, Nj.x, fmaf(niy, Nj.y, niz * Nj.z)));

            // ---- cat store: stage per-warp (stride-3 STS = conflict-free),
            //      then 24 lanes emit the warp's 384 B as coalesced STG.128 ----
            cbuf[wid][lane * 3 + 0] = dist;
            cbuf[wid][lane * 3 + 1] = seta;
            cbuf[wid][lane * 3 + 2] = angle;
            __syncwarp();
            if (lane < 24) {
                float4 cv = *reinterpret_cast<float4*>(&cbuf[wid][lane * 4]);
                *reinterpret_cast<float4*>(catRow + (size_t)(j - lane) * 3 + lane * 4) = cv;
            }
            __syncwarp();

            // a_indices: FACTOR_A*acos(r_hat . d_hat); two 4-wide halves
            float ux = dx * linv, uy = dy * linv, uz = dz * linv;
            float4* ap = reinterpret_cast<float4*>(aRow + (size_t)j * KNN);
            {
                float a0 = facos12(fmaf(rkx[0], ux, fmaf(rky[0], uy, rkz[0] * uz)));
                float a1 = facos12(fmaf(rkx[1], ux, fmaf(rky[1], uy, rkz[1] * uz)));
                float a2 = facos12(fmaf(rkx[2], ux, fmaf(rky[2], uy, rkz[2] * uz)));
                float a3 = facos12(fmaf(rkx[3], ux, fmaf(rky[3], uy, rkz[3] * uz)));
                ap[0] = make_float4(a0, a1, a2, a3);
            }
            {
                float a4 = facos12(fmaf(rkx[4], ux, fmaf(rky[4], uy, rkz[4] * uz)));
                float a5 = facos12(fmaf(rkx[5], ux, fmaf(rky[5], uy, rkz[5] * uz)));
                float a6 = facos12(fmaf(rkx[6], ux, fmaf(rky[6], uy, rkz[6] * uz)));
                float a7 = facos12(fmaf(rkx[7], ux, fmaf(rky[7], uy, rkz[7] * uz)));
                ap[1] = make_float4(a4, a5, a6, a7);
            }
        }

        // ---- diagonal fixup by a thread of the SAME warp that staged column i.
        //      The __syncwarp after the staging STG orders the fixup store after
        //      the warp's STG.128 covering element 3i; other warps never touch
        //      column i of this row.
        if (tid == (i & (THREADS - 1))) {
            catRow[3 * i + 0] = 0.0f;               // dist diag (ref: exactly 0)
            float4* ap = reinterpret_cast<float4*>(aRow + (size_t)i * KNN);
            float4 z = make_float4(0.0f, 0.0f, 0.0f, 0.0f);
            ap[0] = z;                               // a_indices diag = 0 (ref:
            ap[1] = z;                               // arctan2(+0,+0) = 0)
        }
        // NO trailing barrier. Proof of safety for smem reuse next row:
        //  - cbuf[wid] is warp-private; the two __syncwarp()s order its reuse.
        //  - wval[wid]: rewritten by warp wid only after the CURRENT post-B2
        //    __syncthreads, which warp 0 passes only after its B2 reads.
        //  - rkv: rewritten by warp 0 only after NEXT row's post-B1
        //    __syncthreads, which requires every warp to have finished its
        //    rk register copy (it precedes phase C, which precedes next B1).
    }
}

extern "C" void kernel_launch(void* const* d_in, const int* in_sizes, int n_in,
                              void* d_out, int out_size)
{
    const float* points  = (const float*)d_in[0];
    const float* normals = (const float*)d_in[1];
    (void)in_sizes; (void)n_in; (void)out_size;

    float* out  = (float*)d_out;
    float* cat  = out;                                   // [B,N,N,3]
    float* aidx = out + (size_t)BATCH * NPTS * NPTS * 3; // [B,N,N,K]

    gse_kernel<<<BATCH * (NPTS / TI), THREADS>>>(points, normals, cat, aidx);
}